// round 8
// baseline (speedup 1.0000x reference)
#include <cuda_runtime.h>
#include <cuda_bf16.h>
#include <cstdint>

#define NN 2048
#define NELEM (NN*NN)
#define MBIG 8192
#define NSCALED 5

// ---------------- device scratch ----------------
__device__ float g_X[NELEM];
__device__ float g_Y[NELEM];
__device__ float g_M[NELEM];
__device__ __nv_bfloat16 g_Mbf[NELEM];    // M hi
__device__ __nv_bfloat16 g_Mlo[NELEM];    // M lo
__device__ __nv_bfloat16 g_Tbf[NELEM];
__device__ __nv_bfloat16 g_Xbf0[NELEM];
__device__ __nv_bfloat16 g_Xbf1[NELEM];
__device__ __nv_bfloat16 g_Xlo0[NELEM];
__device__ __nv_bfloat16 g_Xlo1[NELEM];
__device__ __nv_bfloat16 g_xhi[(size_t)MBIG*NN];
__device__ __nv_bfloat16 g_xlo[(size_t)MBIG*NN];
__device__ float g_v[NN];
__device__ float g_u[NN];
__device__ float g_s[4];
__device__ float g_coef[2*NSCALED];

__device__ __forceinline__ uint32_t smem_u32(const void* p) {
    uint32_t a;
    asm("{ .reg .u64 t; cvta.to.shared.u64 t, %1; cvt.u32.u64 %0, t; }" : "=r"(a) : "l"(p));
    return a;
}

// ---------------- small kernels ----------------
__global__ void build_M_kernel(const float* __restrict__ w) {
    int j = blockIdx.x * blockDim.x + threadIdx.x;
    int i = blockIdx.y;
    float a = w[(size_t)i * NN + j] - w[(size_t)j * NN + i];
    float m = (i == j ? 1.0f : 0.0f) - a;
    size_t off = (size_t)i * NN + j;
    g_M[off] = m;
    __nv_bfloat16 hi = __float2bfloat16(m);
    g_Mbf[off] = hi;
    g_Mlo[off] = __float2bfloat16(m - __bfloat162float(hi));
}

__global__ void init_v_kernel() {
    int i = blockIdx.x * blockDim.x + threadIdx.x;
    unsigned h = (unsigned)i * 2654435761u;
    h ^= h >> 16; h *= 2246822519u; h ^= h >> 13;
    g_v[i] = ((h & 0xFFFFFF) / 16777216.0f) - 0.5f;
}

// out = scale * (in - M@in);  4 warps per row, block = 2 rows
__global__ void matvec_A_kernel(int dst_is_u, float scale) {
    __shared__ float part[8];
    const float* in  = dst_is_u ? g_v : g_u;
    float*       out = dst_is_u ? g_u : g_v;
    int wid = threadIdx.x >> 5, lid = threadIdx.x & 31;
    int row = blockIdx.x * 2 + (wid >> 2);
    int q = wid & 3;
    const __nv_bfloat162* Mrow = (const __nv_bfloat162*)(g_Mbf + (size_t)row * NN);
    float s = 0.f;
    #pragma unroll
    for (int jj = 0; jj < 8; jj++) {
        int j = q * 256 + jj * 32 + lid;
        __nv_bfloat162 m2 = Mrow[j];
        s += __bfloat162float(m2.x) * in[2*j] + __bfloat162float(m2.y) * in[2*j+1];
    }
    #pragma unroll
    for (int o = 16; o > 0; o >>= 1) s += __shfl_xor_sync(0xFFFFFFFFu, s, o);
    if (lid == 0) part[wid] = s;
    __syncthreads();
    if (threadIdx.x < 2) {
        int r = blockIdx.x * 2 + threadIdx.x;
        float t = part[threadIdx.x*4] + part[threadIdx.x*4+1] + part[threadIdx.x*4+2] + part[threadIdx.x*4+3];
        out[r] = scale * (in[r] - t);
    }
}

// sigma^2 -> c + scaled-Newton coefficient schedule
__global__ void dots_and_c_kernel() {
    __shared__ float r0[1024], r1[1024];
    int t = threadIdx.x;
    float a = 0.f, b = 0.f;
    for (int i = t; i < NN; i += 1024) { float vv = g_v[i], uu = g_u[i]; a += vv*vv; b += uu*uu; }
    r0[t] = a; r1[t] = b;
    __syncthreads();
    for (int off = 512; off > 0; off >>= 1) {
        if (t < off) { r0[t] += r0[t+off]; r1[t] += r1[t+off]; }
        __syncthreads();
    }
    if (t == 0) {
        float sigma2 = r1[0] / (r0[0] + 1e-30f);
        float u = 1.6f * sigma2;
        float c = 2.0f / (2.0f + u);
        g_s[2] = c;
        float lo = c, hi = c * (1.0f + u);
        #pragma unroll
        for (int k = 0; k < NSCALED; k++) {
            float s = 2.0f / (lo + hi);
            g_coef[2*k]   = -s * s;
            g_coef[2*k+1] = 2.0f * s;
            float sl = s * lo;
            lo = sl * (2.0f - sl);
            hi = 1.0f;
        }
    }
}

__global__ void init_X0_kernel() {   // X0 = c * M^T  (fp32 + bf16 hi)
    __shared__ float tile[32][33];
    int bx = blockIdx.x * 32, by = blockIdx.y * 32;
    #pragma unroll
    for (int dy = 0; dy < 32; dy += 8)
        tile[threadIdx.y + dy][threadIdx.x] = g_M[(size_t)(by + threadIdx.y + dy) * NN + bx + threadIdx.x];
    __syncthreads();
    float c = g_s[2];
    #pragma unroll
    for (int dy = 0; dy < 32; dy += 8) {
        float v = c * tile[threadIdx.x][threadIdx.y + dy];
        size_t off = (size_t)(bx + threadIdx.y + dy) * NN + by + threadIdx.x;
        g_X[off] = v;
        g_Xbf0[off] = __float2bfloat16(v);
    }
}

// x fp32 -> xhi, xlo arrays
__global__ void conv_xsplit_kernel(const float* __restrict__ x) {
    size_t i = ((size_t)blockIdx.x * blockDim.x + threadIdx.x) * 4;
    float4 v = *(const float4*)(x + i);
    __nv_bfloat162 hi0, hi1, lo0, lo1;
    hi0.x = __float2bfloat16(v.x); lo0.x = __float2bfloat16(v.x - __bfloat162float(hi0.x));
    hi0.y = __float2bfloat16(v.y); lo0.y = __float2bfloat16(v.y - __bfloat162float(hi0.y));
    hi1.x = __float2bfloat16(v.z); lo1.x = __float2bfloat16(v.z - __bfloat162float(hi1.x));
    hi1.y = __float2bfloat16(v.w); lo1.y = __float2bfloat16(v.w - __bfloat162float(hi1.y));
    *(__nv_bfloat162*)(g_xhi + i)     = hi0;
    *(__nv_bfloat162*)(g_xhi + i + 2) = hi1;
    *(__nv_bfloat162*)(g_xlo + i)     = lo0;
    *(__nv_bfloat162*)(g_xlo + i + 2) = lo1;
}

// ---------------- mma.sync bf16 GEMM: CTA 128x256, warp 64x64, 4-stage ----------------
// acc[m][n] = sum_k Aseg[m][k] * Bseg'[k][n]
//   BMODE 0: B K-major (row stride NN); BMODE 1: B row-major (row stride Ndim), trans ldmatrix
#define SK 40
#define ASZ (128*SK*2)          // 10240
#define BSZ0 (256*SK*2)         // 20480 (K-major B: 256 rows x 80B)
#define BT_STRIDE 528           // trans B: 32 rows x (512+16)B
#define BSZ 20480
#define NSTAGE 4
#define GSMEM (NSTAGE*(ASZ+BSZ))

template<int BMODE>
__global__ void __launch_bounds__(256, 1) mma_gemm_kernel(
    float* outF, __nv_bfloat16* outB, __nv_bfloat16* outBlo,
    const __nv_bfloat16* __restrict__ A0, const __nv_bfloat16* __restrict__ A1,
    const __nv_bfloat16* __restrict__ A2,
    const __nv_bfloat16* __restrict__ B0, const __nv_bfloat16* __restrict__ B1,
    const __nv_bfloat16* __restrict__ B2,
    const float* __restrict__ Dext, const float* __restrict__ bias,
    const float* __restrict__ coefp,
    int Ndim, int Kdim, float alpha, float beta, int addI)
{
    extern __shared__ __align__(16) char smem[];
    uint32_t sbase = smem_u32(smem);
    int tid = threadIdx.x;
    int wid = tid >> 5, lid = tid & 31;
    int warp_m = wid >> 2, warp_n = wid & 3;      // 2 x 4, warp tile 64x64
    int bm = blockIdx.y * 128, bn = blockIdx.x * 256;

    float acc[4][8][4];
    #pragma unroll
    for (int i = 0; i < 4; i++)
        #pragma unroll
        for (int j = 0; j < 8; j++)
            #pragma unroll
            for (int r = 0; r < 4; r++) acc[i][j][r] = 0.f;

    auto load_stage = [&](int stage, int kt) {
        int seg = kt >> 11;
        int kc0 = kt & (NN - 1);
        const __nv_bfloat16* As = (seg == 0) ? A0 : ((seg == 1) ? A1 : A2);
        const __nv_bfloat16* Bs = (seg == 0) ? B0 : ((seg == 1) ? B1 : B2);
        uint32_t sA = sbase + stage * (ASZ + BSZ);
        uint32_t sB = sA + ASZ;
        #pragma unroll
        for (int s = 0; s < 2; s++) {               // A: 512 chunks
            int c = tid + s * 256;
            int row = c >> 2, kc = c & 3;
            const char* gA = (const char*)(As + (size_t)(bm + row) * NN + kc0 + kc * 8);
            uint32_t dA = sA + row * (SK*2) + kc * 16;
            asm volatile("cp.async.cg.shared.global [%0], [%1], 16;" :: "r"(dA), "l"(gA));
        }
        #pragma unroll
        for (int s = 0; s < 4; s++) {               // B: 1024 chunks
            int c = tid + s * 256;
            if (BMODE == 0) {
                int row = c >> 2, kc = c & 3;
                const char* gB = (const char*)(Bs + (size_t)(bn + row) * NN + kc0 + kc * 8);
                uint32_t dB = sB + row * (SK*2) + kc * 16;
                asm volatile("cp.async.cg.shared.global [%0], [%1], 16;" :: "r"(dB), "l"(gB));
            } else {
                int r = c >> 5, nch = c & 31;
                const char* gB = (const char*)(Bs + (size_t)(kc0 + r) * Ndim + bn + nch * 8);
                uint32_t dB = sB + r * BT_STRIDE + nch * 16;
                asm volatile("cp.async.cg.shared.global [%0], [%1], 16;" :: "r"(dB), "l"(gB));
            }
        }
        asm volatile("cp.async.commit_group;" ::: "memory");
    };

    const int NB = Kdim >> 5;
    #pragma unroll
    for (int s = 0; s < NSTAGE - 1; s++) load_stage(s, s * 32);

    uint32_t a_lane_off = (uint32_t)((lid & 15) * (SK*2) + ((lid >> 4) & 1) * 16);
    uint32_t b_lane_off0 = (uint32_t)((((lid & 7) + ((lid >> 4) & 1) * 8) * (SK*2)) + (((lid >> 3) & 1) * 16));
    int bg = lid >> 3, bw = lid & 7;
    uint32_t bt_krow = (uint32_t)((bg & 1) * 8 + bw);
    uint32_t bt_ncol = (uint32_t)((bg >> 1) * 8);

    for (int kb = 0; kb < NB; kb++) {
        if (kb >= NB - (NSTAGE - 1)) asm volatile("cp.async.wait_group 0;" ::: "memory");
        else                         asm volatile("cp.async.wait_group %0;" :: "n"(NSTAGE - 2) : "memory");
        __syncthreads();

        int nkt = kb + NSTAGE - 1;
        if (nkt < NB) load_stage(nkt % NSTAGE, nkt * 32);

        int stage = kb % NSTAGE;
        uint32_t sA = sbase + stage * (ASZ + BSZ) + warp_m * 64 * (SK*2);
        uint32_t sBb = sbase + stage * (ASZ + BSZ) + ASZ;

        #pragma unroll
        for (int kk = 0; kk < 2; kk++) {
            uint32_t af[4][4], bf[4][4];
            #pragma unroll
            for (int mi = 0; mi < 4; mi++) {
                uint32_t addr = sA + mi * 16 * (SK*2) + kk * 32 + a_lane_off;
                asm volatile("ldmatrix.sync.aligned.m8n8.x4.shared.b16 {%0,%1,%2,%3}, [%4];"
                    : "=r"(af[mi][0]), "=r"(af[mi][1]), "=r"(af[mi][2]), "=r"(af[mi][3]) : "r"(addr));
            }
            #pragma unroll
            for (int nj = 0; nj < 4; nj++) {
                if (BMODE == 0) {
                    uint32_t addr = sBb + (warp_n * 64 + nj * 16) * (SK*2) + kk * 32 + b_lane_off0;
                    asm volatile("ldmatrix.sync.aligned.m8n8.x4.shared.b16 {%0,%1,%2,%3}, [%4];"
                        : "=r"(bf[nj][0]), "=r"(bf[nj][1]), "=r"(bf[nj][2]), "=r"(bf[nj][3]) : "r"(addr));
                } else {
                    uint32_t addr = sBb + (kk * 16 + bt_krow) * BT_STRIDE
                                  + (warp_n * 64 + nj * 16 + bt_ncol) * 2;
                    asm volatile("ldmatrix.sync.aligned.m8n8.x4.trans.shared.b16 {%0,%1,%2,%3}, [%4];"
                        : "=r"(bf[nj][0]), "=r"(bf[nj][1]), "=r"(bf[nj][2]), "=r"(bf[nj][3]) : "r"(addr));
                }
            }
            #pragma unroll
            for (int mi = 0; mi < 4; mi++) {
                #pragma unroll
                for (int nj = 0; nj < 8; nj++) {
                    uint32_t b0 = bf[nj >> 1][(nj & 1) ? 2 : 0];
                    uint32_t b1 = bf[nj >> 1][(nj & 1) ? 3 : 1];
                    asm volatile(
                        "mma.sync.aligned.m16n8k16.row.col.f32.bf16.bf16.f32 "
                        "{%0,%1,%2,%3}, {%4,%5,%6,%7}, {%8,%9}, {%0,%1,%2,%3};"
                        : "+f"(acc[mi][nj][0]), "+f"(acc[mi][nj][1]),
                          "+f"(acc[mi][nj][2]), "+f"(acc[mi][nj][3])
                        : "r"(af[mi][0]), "r"(af[mi][1]), "r"(af[mi][2]), "r"(af[mi][3]),
                          "r"(b0), "r"(b1));
                }
            }
        }
    }

    if (coefp) { alpha = coefp[0]; beta = coefp[1]; }

    int lrow = lid >> 2, lcol = (lid & 3) * 2;
    #pragma unroll
    for (int mi = 0; mi < 4; mi++) {
        #pragma unroll
        for (int half = 0; half < 2; half++) {
            int row = bm + warp_m * 64 + mi * 16 + lrow + half * 8;
            #pragma unroll
            for (int nj = 0; nj < 8; nj++) {
                int col = bn + warp_n * 64 + nj * 8 + lcol;
                size_t off = (size_t)row * Ndim + col;
                float2 o;
                o.x = alpha * acc[mi][nj][half * 2 + 0];
                o.y = alpha * acc[mi][nj][half * 2 + 1];
                if (Dext) {
                    float2 d2 = *(const float2*)(Dext + off);
                    o.x += beta * d2.x; o.y += beta * d2.y;
                }
                if (bias) {
                    float2 b2 = *(const float2*)(bias + col);
                    o.x += b2.x; o.y += b2.y;
                }
                if (addI) {
                    if (row == col)     o.x += 1.f;
                    if (row == col + 1) o.y += 1.f;
                }
                if (outF) *(float2*)(outF + off) = o;
                if (outB || outBlo) {
                    __nv_bfloat162 h;
                    h.x = __float2bfloat16(o.x); h.y = __float2bfloat16(o.y);
                    if (outB) *(__nv_bfloat162*)(outB + off) = h;
                    if (outBlo) {
                        __nv_bfloat162 l;
                        l.x = __float2bfloat16(o.x - __bfloat162float(h.x));
                        l.y = __float2bfloat16(o.y - __bfloat162float(h.y));
                        *(__nv_bfloat162*)(outBlo + off) = l;
                    }
                }
            }
        }
    }
}

// ---------------- launch ----------------
extern "C" void kernel_launch(void* const* d_in, const int* in_sizes, int n_in,
                              void* d_out, int out_size) {
    const float* x      = (const float*)d_in[0];
    const float* weight = (const float*)d_in[1];
    const float* bias   = (const float*)d_in[2];
    float* out = (float*)d_out;

    float *pX, *pY, *pCoef;
    __nv_bfloat16 *pMbf, *pMlo, *pTbf, *pXb0, *pXb1, *pXl0, *pXl1, *pxhi, *pxlo;
    cudaGetSymbolAddress((void**)&pX, g_X);
    cudaGetSymbolAddress((void**)&pY, g_Y);
    cudaGetSymbolAddress((void**)&pCoef, g_coef);
    cudaGetSymbolAddress((void**)&pMbf, g_Mbf);
    cudaGetSymbolAddress((void**)&pMlo, g_Mlo);
    cudaGetSymbolAddress((void**)&pTbf, g_Tbf);
    cudaGetSymbolAddress((void**)&pXb0, g_Xbf0);
    cudaGetSymbolAddress((void**)&pXb1, g_Xbf1);
    cudaGetSymbolAddress((void**)&pXl0, g_Xlo0);
    cudaGetSymbolAddress((void**)&pXl1, g_Xlo1);
    cudaGetSymbolAddress((void**)&pxhi, g_xhi);
    cudaGetSymbolAddress((void**)&pxlo, g_xlo);

    cudaFuncSetAttribute(mma_gemm_kernel<0>, cudaFuncAttributeMaxDynamicSharedMemorySize, GSMEM);
    cudaFuncSetAttribute(mma_gemm_kernel<1>, cudaFuncAttributeMaxDynamicSharedMemorySize, GSMEM);

    // 1. M = I - (w - w^T)
    build_M_kernel<<<dim3(NN/256, NN), 256>>>(weight);

    // 2. power iteration (4 pairs) -> sigma^2, c, schedule
    init_v_kernel<<<NN/256, 256>>>();
    for (int it = 0; it < 4; it++) {
        matvec_A_kernel<<<NN/2, 256>>>(1, 1.0f);
        matvec_A_kernel<<<NN/2, 256>>>(0, 1.0f / 64.0f);
    }
    matvec_A_kernel<<<NN/2, 256>>>(1, 1.0f);
    dots_and_c_kernel<<<1, 1024>>>();

    // 3. X0 = c * M^T
    init_X0_kernel<<<dim3(NN/32, NN/32), dim3(32, 8)>>>();

    dim3 g2k(NN/256, NN/128);          // 8 x 16 = 128 CTAs
    float *Xf = pX, *Xfn = pY;
    __nv_bfloat16 *Xb = pXb0, *Xbn = pXb1;
    __nv_bfloat16 *Xl = pXl0, *Xln = pXl1;

    // 4a. scaled Newton bf16, 5 iters
    for (int it = 0; it < NSCALED; it++) {
        bool last = (it == NSCALED - 1);
        mma_gemm_kernel<1><<<g2k, 256, GSMEM>>>(nullptr, pTbf, nullptr,
                                                pMbf, pMbf, pMbf, Xb, Xb, Xb,
                                                nullptr, nullptr, nullptr,
                                                NN, NN, 1.0f, 0.0f, 0);
        mma_gemm_kernel<1><<<g2k, 256, GSMEM>>>(Xfn, Xbn, last ? Xln : nullptr,
                                                Xb, Xb, Xb, pTbf, pTbf, pTbf,
                                                Xf, nullptr, pCoef + 2*it,
                                                NN, NN, 0.f, 0.f, 0);
        float* tf = Xf; Xf = Xfn; Xfn = tf;
        __nv_bfloat16* tb = Xb; Xb = Xbn; Xbn = tb;
        if (last) { __nv_bfloat16* tl = Xl; Xl = Xln; Xln = tl; }
    }

    // 4b. single strengthened polish
    mma_gemm_kernel<1><<<g2k, 256, GSMEM>>>(nullptr, pTbf, nullptr,
                                            pMbf, pMlo, pMbf, Xb, Xb, Xl,
                                            nullptr, nullptr, nullptr,
                                            NN, 3*NN, -1.0f, 0.0f, 1);
    mma_gemm_kernel<1><<<g2k, 256, GSMEM>>>(nullptr, Xbn, Xln,
                                            Xb, Xl, Xl, pTbf, pTbf, pTbf,
                                            Xf, nullptr, nullptr,
                                            NN, 2*NN, 1.0f, 1.0f, 0);
    Xb = Xbn; Xl = Xln;

    // 5. out = 2*(x @ X^T) - x + bias
    conv_xsplit_kernel<<<((size_t)MBIG*NN/4)/256, 256>>>(x);
    mma_gemm_kernel<0><<<dim3(NN/256, MBIG/128), 256, GSMEM>>>(out, nullptr, nullptr,
                                                               pxhi, pxlo, pxhi, Xb, Xb, Xl,
                                                               x, bias, nullptr,
                                                               NN, 3*NN, 2.0f, -1.0f, 0);
}

// round 9
// speedup vs baseline: 1.3321x; 1.3321x over previous
#include <cuda_runtime.h>
#include <cuda_bf16.h>
#include <cstdint>

#define NN 2048
#define NELEM (NN*NN)
#define MBIG 8192
#define NSCALED 5

// ---------------- device scratch ----------------
__device__ float g_X[NELEM];
__device__ float g_Y[NELEM];
__device__ float g_M[NELEM];
__device__ __nv_bfloat16 g_Mbf[NELEM];    // M hi
__device__ __nv_bfloat16 g_Mlo[NELEM];    // M lo
__device__ __nv_bfloat16 g_Tbf[NELEM];
__device__ __nv_bfloat16 g_Xbf0[NELEM];
__device__ __nv_bfloat16 g_Xbf1[NELEM];
__device__ __nv_bfloat16 g_Xlo0[NELEM];
__device__ __nv_bfloat16 g_Xlo1[NELEM];
__device__ __nv_bfloat16 g_xhi[(size_t)MBIG*NN];
__device__ __nv_bfloat16 g_xlo[(size_t)MBIG*NN];
__device__ float g_v[NN];
__device__ float g_u[NN];
__device__ float g_s[4];
__device__ float g_coef[2*NSCALED];

__device__ __forceinline__ uint32_t smem_u32(const void* p) {
    uint32_t a;
    asm("{ .reg .u64 t; cvta.to.shared.u64 t, %1; cvt.u32.u64 %0, t; }" : "=r"(a) : "l"(p));
    return a;
}

// ---------------- small kernels ----------------
__global__ void build_M_kernel(const float* __restrict__ w) {
    int j = blockIdx.x * blockDim.x + threadIdx.x;
    int i = blockIdx.y;
    float a = w[(size_t)i * NN + j] - w[(size_t)j * NN + i];
    float m = (i == j ? 1.0f : 0.0f) - a;
    size_t off = (size_t)i * NN + j;
    g_M[off] = m;
    __nv_bfloat16 hi = __float2bfloat16(m);
    g_Mbf[off] = hi;
    g_Mlo[off] = __float2bfloat16(m - __bfloat162float(hi));
}

__global__ void init_v_kernel() {
    int i = blockIdx.x * blockDim.x + threadIdx.x;
    unsigned h = (unsigned)i * 2654435761u;
    h ^= h >> 16; h *= 2246822519u; h ^= h >> 13;
    g_v[i] = ((h & 0xFFFFFF) / 16777216.0f) - 0.5f;
}

// out = scale * (in - M@in);  4 warps per row, block = 2 rows
__global__ void matvec_A_kernel(int dst_is_u, float scale) {
    __shared__ float part[8];
    const float* in  = dst_is_u ? g_v : g_u;
    float*       out = dst_is_u ? g_u : g_v;
    int wid = threadIdx.x >> 5, lid = threadIdx.x & 31;
    int row = blockIdx.x * 2 + (wid >> 2);
    int q = wid & 3;
    const __nv_bfloat162* Mrow = (const __nv_bfloat162*)(g_Mbf + (size_t)row * NN);
    float s = 0.f;
    #pragma unroll
    for (int jj = 0; jj < 8; jj++) {
        int j = q * 256 + jj * 32 + lid;
        __nv_bfloat162 m2 = Mrow[j];
        s += __bfloat162float(m2.x) * in[2*j] + __bfloat162float(m2.y) * in[2*j+1];
    }
    #pragma unroll
    for (int o = 16; o > 0; o >>= 1) s += __shfl_xor_sync(0xFFFFFFFFu, s, o);
    if (lid == 0) part[wid] = s;
    __syncthreads();
    if (threadIdx.x < 2) {
        int r = blockIdx.x * 2 + threadIdx.x;
        float t = part[threadIdx.x*4] + part[threadIdx.x*4+1] + part[threadIdx.x*4+2] + part[threadIdx.x*4+3];
        out[r] = scale * (in[r] - t);
    }
}

// sigma^2 -> c + scaled-Newton coefficient schedule
__global__ void dots_and_c_kernel() {
    __shared__ float r0[1024], r1[1024];
    int t = threadIdx.x;
    float a = 0.f, b = 0.f;
    for (int i = t; i < NN; i += 1024) { float vv = g_v[i], uu = g_u[i]; a += vv*vv; b += uu*uu; }
    r0[t] = a; r1[t] = b;
    __syncthreads();
    for (int off = 512; off > 0; off >>= 1) {
        if (t < off) { r0[t] += r0[t+off]; r1[t] += r1[t+off]; }
        __syncthreads();
    }
    if (t == 0) {
        float sigma2 = r1[0] / (r0[0] + 1e-30f);
        float u = 1.6f * sigma2;
        float c = 2.0f / (2.0f + u);
        g_s[2] = c;
        float lo = c, hi = c * (1.0f + u);
        #pragma unroll
        for (int k = 0; k < NSCALED; k++) {
            float s = 2.0f / (lo + hi);
            g_coef[2*k]   = -s * s;
            g_coef[2*k+1] = 2.0f * s;
            float sl = s * lo;
            lo = sl * (2.0f - sl);
            hi = 1.0f;
        }
    }
}

__global__ void init_X0_kernel() {   // X0 = c * M^T  (fp32 + bf16 hi)
    __shared__ float tile[32][33];
    int bx = blockIdx.x * 32, by = blockIdx.y * 32;
    #pragma unroll
    for (int dy = 0; dy < 32; dy += 8)
        tile[threadIdx.y + dy][threadIdx.x] = g_M[(size_t)(by + threadIdx.y + dy) * NN + bx + threadIdx.x];
    __syncthreads();
    float c = g_s[2];
    #pragma unroll
    for (int dy = 0; dy < 32; dy += 8) {
        float v = c * tile[threadIdx.x][threadIdx.y + dy];
        size_t off = (size_t)(bx + threadIdx.y + dy) * NN + by + threadIdx.x;
        g_X[off] = v;
        g_Xbf0[off] = __float2bfloat16(v);
    }
}

// x fp32 -> xhi, xlo arrays
__global__ void conv_xsplit_kernel(const float* __restrict__ x) {
    size_t i = ((size_t)blockIdx.x * blockDim.x + threadIdx.x) * 4;
    float4 v = *(const float4*)(x + i);
    __nv_bfloat162 hi0, hi1, lo0, lo1;
    hi0.x = __float2bfloat16(v.x); lo0.x = __float2bfloat16(v.x - __bfloat162float(hi0.x));
    hi0.y = __float2bfloat16(v.y); lo0.y = __float2bfloat16(v.y - __bfloat162float(hi0.y));
    hi1.x = __float2bfloat16(v.z); lo1.x = __float2bfloat16(v.z - __bfloat162float(hi1.x));
    hi1.y = __float2bfloat16(v.w); lo1.y = __float2bfloat16(v.w - __bfloat162float(hi1.y));
    *(__nv_bfloat162*)(g_xhi + i)     = hi0;
    *(__nv_bfloat162*)(g_xhi + i + 2) = hi1;
    *(__nv_bfloat162*)(g_xlo + i)     = lo0;
    *(__nv_bfloat162*)(g_xlo + i + 2) = lo1;
}

// ---------------- mma.sync bf16 GEMM: CTA 128x128, 4 warps (2x2) of 64x64, 5-stage ----------------
// acc[m][n] = sum_k Aseg[m][k] * Bseg'[k][n]
//   BMODE 0: B K-major (row stride NN); BMODE 1: B row-major (row stride Ndim), trans ldmatrix
#define SK 40
#define ASZ (128*SK*2)          // 10240
#define BSZ 10240
#define BT_STRIDE 272
#define NSTAGE 5
#define GSMEM (NSTAGE*(ASZ+BSZ))   // 102400

template<int BMODE>
__global__ void __launch_bounds__(128, 2) mma_gemm_kernel(
    float* outF, __nv_bfloat16* outB, __nv_bfloat16* outBlo,
    const __nv_bfloat16* __restrict__ A0, const __nv_bfloat16* __restrict__ A1,
    const __nv_bfloat16* __restrict__ A2,
    const __nv_bfloat16* __restrict__ B0, const __nv_bfloat16* __restrict__ B1,
    const __nv_bfloat16* __restrict__ B2,
    const float* __restrict__ Dext, const float* __restrict__ bias,
    const float* __restrict__ coefp,
    int Ndim, int Kdim, float alpha, float beta, int addI)
{
    extern __shared__ __align__(16) char smem[];
    uint32_t sbase = smem_u32(smem);
    int tid = threadIdx.x;
    int wid = tid >> 5, lid = tid & 31;
    int warp_m = wid >> 1, warp_n = wid & 1;      // 2 x 2, warp tile 64x64
    int bm = blockIdx.y * 128, bn = blockIdx.x * 128;

    float acc[4][8][4];
    #pragma unroll
    for (int i = 0; i < 4; i++)
        #pragma unroll
        for (int j = 0; j < 8; j++)
            #pragma unroll
            for (int r = 0; r < 4; r++) acc[i][j][r] = 0.f;

    auto load_stage = [&](int stage, int kt) {
        int seg = kt >> 11;
        int kc0 = kt & (NN - 1);
        const __nv_bfloat16* As = (seg == 0) ? A0 : ((seg == 1) ? A1 : A2);
        const __nv_bfloat16* Bs = (seg == 0) ? B0 : ((seg == 1) ? B1 : B2);
        uint32_t sA = sbase + stage * (ASZ + BSZ);
        uint32_t sB = sA + ASZ;
        #pragma unroll
        for (int s = 0; s < 4; s++) {               // A: 512 chunks, 128 threads
            int c = tid + s * 128;
            int row = c >> 2, kc = c & 3;
            const char* gA = (const char*)(As + (size_t)(bm + row) * NN + kc0 + kc * 8);
            uint32_t dA = sA + row * (SK*2) + kc * 16;
            asm volatile("cp.async.cg.shared.global [%0], [%1], 16;" :: "r"(dA), "l"(gA));
        }
        #pragma unroll
        for (int s = 0; s < 4; s++) {               // B: 512 chunks
            int c = tid + s * 128;
            if (BMODE == 0) {
                int row = c >> 2, kc = c & 3;
                const char* gB = (const char*)(Bs + (size_t)(bn + row) * NN + kc0 + kc * 8);
                uint32_t dB = sB + row * (SK*2) + kc * 16;
                asm volatile("cp.async.cg.shared.global [%0], [%1], 16;" :: "r"(dB), "l"(gB));
            } else {
                int r = c >> 4, nch = c & 15;
                const char* gB = (const char*)(Bs + (size_t)(kc0 + r) * Ndim + bn + nch * 8);
                uint32_t dB = sB + r * BT_STRIDE + nch * 16;
                asm volatile("cp.async.cg.shared.global [%0], [%1], 16;" :: "r"(dB), "l"(gB));
            }
        }
        asm volatile("cp.async.commit_group;" ::: "memory");
    };

    const int NB = Kdim >> 5;
    #pragma unroll
    for (int s = 0; s < NSTAGE - 1; s++) load_stage(s, s * 32);

    uint32_t a_lane_off = (uint32_t)((lid & 15) * (SK*2) + ((lid >> 4) & 1) * 16);
    uint32_t b_lane_off0 = (uint32_t)((((lid & 7) + ((lid >> 4) & 1) * 8) * (SK*2)) + (((lid >> 3) & 1) * 16));
    int bg = lid >> 3, bw = lid & 7;
    uint32_t bt_krow = (uint32_t)((bg & 1) * 8 + bw);
    uint32_t bt_ncol = (uint32_t)((bg >> 1) * 8);

    for (int kb = 0; kb < NB; kb++) {
        if (kb >= NB - (NSTAGE - 1)) asm volatile("cp.async.wait_group 0;" ::: "memory");
        else                         asm volatile("cp.async.wait_group %0;" :: "n"(NSTAGE - 2) : "memory");
        __syncthreads();

        int nkt = kb + NSTAGE - 1;
        if (nkt < NB) load_stage(nkt % NSTAGE, nkt * 32);

        int stage = kb % NSTAGE;
        uint32_t sA = sbase + stage * (ASZ + BSZ) + warp_m * 64 * (SK*2);
        uint32_t sBb = sbase + stage * (ASZ + BSZ) + ASZ;

        #pragma unroll
        for (int kk = 0; kk < 2; kk++) {
            uint32_t af[4][4], bf[4][4];
            #pragma unroll
            for (int mi = 0; mi < 4; mi++) {
                uint32_t addr = sA + mi * 16 * (SK*2) + kk * 32 + a_lane_off;
                asm volatile("ldmatrix.sync.aligned.m8n8.x4.shared.b16 {%0,%1,%2,%3}, [%4];"
                    : "=r"(af[mi][0]), "=r"(af[mi][1]), "=r"(af[mi][2]), "=r"(af[mi][3]) : "r"(addr));
            }
            #pragma unroll
            for (int nj = 0; nj < 4; nj++) {
                if (BMODE == 0) {
                    uint32_t addr = sBb + (warp_n * 64 + nj * 16) * (SK*2) + kk * 32 + b_lane_off0;
                    asm volatile("ldmatrix.sync.aligned.m8n8.x4.shared.b16 {%0,%1,%2,%3}, [%4];"
                        : "=r"(bf[nj][0]), "=r"(bf[nj][1]), "=r"(bf[nj][2]), "=r"(bf[nj][3]) : "r"(addr));
                } else {
                    uint32_t addr = sBb + (kk * 16 + bt_krow) * BT_STRIDE
                                  + (warp_n * 64 + nj * 16 + bt_ncol) * 2;
                    asm volatile("ldmatrix.sync.aligned.m8n8.x4.trans.shared.b16 {%0,%1,%2,%3}, [%4];"
                        : "=r"(bf[nj][0]), "=r"(bf[nj][1]), "=r"(bf[nj][2]), "=r"(bf[nj][3]) : "r"(addr));
                }
            }
            #pragma unroll
            for (int mi = 0; mi < 4; mi++) {
                #pragma unroll
                for (int nj = 0; nj < 8; nj++) {
                    uint32_t b0 = bf[nj >> 1][(nj & 1) ? 2 : 0];
                    uint32_t b1 = bf[nj >> 1][(nj & 1) ? 3 : 1];
                    asm volatile(
                        "mma.sync.aligned.m16n8k16.row.col.f32.bf16.bf16.f32 "
                        "{%0,%1,%2,%3}, {%4,%5,%6,%7}, {%8,%9}, {%0,%1,%2,%3};"
                        : "+f"(acc[mi][nj][0]), "+f"(acc[mi][nj][1]),
                          "+f"(acc[mi][nj][2]), "+f"(acc[mi][nj][3])
                        : "r"(af[mi][0]), "r"(af[mi][1]), "r"(af[mi][2]), "r"(af[mi][3]),
                          "r"(b0), "r"(b1));
                }
            }
        }
    }

    if (coefp) { alpha = coefp[0]; beta = coefp[1]; }

    int lrow = lid >> 2, lcol = (lid & 3) * 2;
    #pragma unroll
    for (int mi = 0; mi < 4; mi++) {
        #pragma unroll
        for (int half = 0; half < 2; half++) {
            int row = bm + warp_m * 64 + mi * 16 + lrow + half * 8;
            #pragma unroll
            for (int nj = 0; nj < 8; nj++) {
                int col = bn + warp_n * 64 + nj * 8 + lcol;
                size_t off = (size_t)row * Ndim + col;
                float2 o;
                o.x = alpha * acc[mi][nj][half * 2 + 0];
                o.y = alpha * acc[mi][nj][half * 2 + 1];
                if (Dext) {
                    float2 d2 = *(const float2*)(Dext + off);
                    o.x += beta * d2.x; o.y += beta * d2.y;
                }
                if (bias) {
                    float2 b2 = *(const float2*)(bias + col);
                    o.x += b2.x; o.y += b2.y;
                }
                if (addI) {
                    if (row == col)     o.x += 1.f;
                    if (row == col + 1) o.y += 1.f;
                }
                if (outF) *(float2*)(outF + off) = o;
                if (outB || outBlo) {
                    __nv_bfloat162 h;
                    h.x = __float2bfloat16(o.x); h.y = __float2bfloat16(o.y);
                    if (outB) *(__nv_bfloat162*)(outB + off) = h;
                    if (outBlo) {
                        __nv_bfloat162 l;
                        l.x = __float2bfloat16(o.x - __bfloat162float(h.x));
                        l.y = __float2bfloat16(o.y - __bfloat162float(h.y));
                        *(__nv_bfloat162*)(outBlo + off) = l;
                    }
                }
            }
        }
    }
}

// ---------------- launch ----------------
extern "C" void kernel_launch(void* const* d_in, const int* in_sizes, int n_in,
                              void* d_out, int out_size) {
    const float* x      = (const float*)d_in[0];
    const float* weight = (const float*)d_in[1];
    const float* bias   = (const float*)d_in[2];
    float* out = (float*)d_out;

    float *pX, *pY, *pCoef;
    __nv_bfloat16 *pMbf, *pMlo, *pTbf, *pXb0, *pXb1, *pXl0, *pXl1, *pxhi, *pxlo;
    cudaGetSymbolAddress((void**)&pX, g_X);
    cudaGetSymbolAddress((void**)&pY, g_Y);
    cudaGetSymbolAddress((void**)&pCoef, g_coef);
    cudaGetSymbolAddress((void**)&pMbf, g_Mbf);
    cudaGetSymbolAddress((void**)&pMlo, g_Mlo);
    cudaGetSymbolAddress((void**)&pTbf, g_Tbf);
    cudaGetSymbolAddress((void**)&pXb0, g_Xbf0);
    cudaGetSymbolAddress((void**)&pXb1, g_Xbf1);
    cudaGetSymbolAddress((void**)&pXl0, g_Xlo0);
    cudaGetSymbolAddress((void**)&pXl1, g_Xlo1);
    cudaGetSymbolAddress((void**)&pxhi, g_xhi);
    cudaGetSymbolAddress((void**)&pxlo, g_xlo);

    cudaFuncSetAttribute(mma_gemm_kernel<0>, cudaFuncAttributeMaxDynamicSharedMemorySize, GSMEM);
    cudaFuncSetAttribute(mma_gemm_kernel<1>, cudaFuncAttributeMaxDynamicSharedMemorySize, GSMEM);

    // 1. M = I - (w - w^T)
    build_M_kernel<<<dim3(NN/256, NN), 256>>>(weight);

    // 2. power iteration (4 pairs) -> sigma^2, c, schedule
    init_v_kernel<<<NN/256, 256>>>();
    for (int it = 0; it < 4; it++) {
        matvec_A_kernel<<<NN/2, 256>>>(1, 1.0f);
        matvec_A_kernel<<<NN/2, 256>>>(0, 1.0f / 64.0f);
    }
    matvec_A_kernel<<<NN/2, 256>>>(1, 1.0f);
    dots_and_c_kernel<<<1, 1024>>>();

    // 3. X0 = c * M^T
    init_X0_kernel<<<dim3(NN/32, NN/32), dim3(32, 8)>>>();

    dim3 g2k(NN/128, NN/128);          // 16 x 16 = 256 CTAs
    float *Xf = pX, *Xfn = pY;
    __nv_bfloat16 *Xb = pXb0, *Xbn = pXb1;
    __nv_bfloat16 *Xl = pXl0, *Xln = pXl1;

    // 4a. scaled Newton bf16, 5 iters
    for (int it = 0; it < NSCALED; it++) {
        bool last = (it == NSCALED - 1);
        mma_gemm_kernel<1><<<g2k, 128, GSMEM>>>(nullptr, pTbf, nullptr,
                                                pMbf, pMbf, pMbf, Xb, Xb, Xb,
                                                nullptr, nullptr, nullptr,
                                                NN, NN, 1.0f, 0.0f, 0);
        mma_gemm_kernel<1><<<g2k, 128, GSMEM>>>(Xfn, Xbn, last ? Xln : nullptr,
                                                Xb, Xb, Xb, pTbf, pTbf, pTbf,
                                                Xf, nullptr, pCoef + 2*it,
                                                NN, NN, 0.f, 0.f, 0);
        float* tf = Xf; Xf = Xfn; Xfn = tf;
        __nv_bfloat16* tb = Xb; Xb = Xbn; Xbn = tb;
        if (last) { __nv_bfloat16* tl = Xl; Xl = Xln; Xln = tl; }
    }

    // 4b. single strengthened polish
    mma_gemm_kernel<1><<<g2k, 128, GSMEM>>>(nullptr, pTbf, nullptr,
                                            pMbf, pMlo, pMbf, Xb, Xb, Xl,
                                            nullptr, nullptr, nullptr,
                                            NN, 3*NN, -1.0f, 0.0f, 1);
    mma_gemm_kernel<1><<<g2k, 128, GSMEM>>>(nullptr, Xbn, Xln,
                                            Xb, Xl, Xl, pTbf, pTbf, pTbf,
                                            Xf, nullptr, nullptr,
                                            NN, 2*NN, 1.0f, 1.0f, 0);
    Xb = Xbn; Xl = Xln;

    // 5. out = 2*(x @ X^T) - x + bias
    conv_xsplit_kernel<<<((size_t)MBIG*NN/4)/256, 256>>>(x);
    mma_gemm_kernel<0><<<dim3(NN/128, MBIG/128), 128, GSMEM>>>(out, nullptr, nullptr,
                                                               pxhi, pxlo, pxhi, Xb, Xb, Xl,
                                                               x, bias, nullptr,
                                                               NN, 3*NN, 2.0f, -1.0f, 0);
}

// round 10
// speedup vs baseline: 1.5917x; 1.1949x over previous
#include <cuda_runtime.h>
#include <cuda_fp16.h>
#include <cstdint>

#define NN 2048
#define NELEM (NN*NN)
#define MBIG 8192
#define NSCALED 5

// ---------------- device scratch ----------------
__device__ float g_X[NELEM];
__device__ float g_Y[NELEM];
__device__ float g_M[NELEM];
__device__ __half g_Mhi[NELEM];
__device__ __half g_Mlo[NELEM];
__device__ __half g_Tbf[NELEM];
__device__ __half g_Xh0[NELEM];
__device__ __half g_Xh1[NELEM];
__device__ __half g_Xl0[NELEM];
__device__ __half g_Xl1[NELEM];
__device__ __half g_xhi[(size_t)MBIG*NN];
__device__ float g_v[NN];
__device__ float g_u[NN];
__device__ float g_s[4];
__device__ float g_coef[2*NSCALED];

__device__ __forceinline__ uint32_t smem_u32(const void* p) {
    uint32_t a;
    asm("{ .reg .u64 t; cvta.to.shared.u64 t, %1; cvt.u32.u64 %0, t; }" : "=r"(a) : "l"(p));
    return a;
}

// ---------------- small kernels ----------------
__global__ void build_M_kernel(const float* __restrict__ w) {
    int j = blockIdx.x * blockDim.x + threadIdx.x;
    int i = blockIdx.y;
    float a = w[(size_t)i * NN + j] - w[(size_t)j * NN + i];
    float m = (i == j ? 1.0f : 0.0f) - a;
    size_t off = (size_t)i * NN + j;
    g_M[off] = m;
    __half hi = __float2half(m);
    g_Mhi[off] = hi;
    g_Mlo[off] = __float2half(m - __half2float(hi));
}

__global__ void init_v_kernel() {
    int i = blockIdx.x * blockDim.x + threadIdx.x;
    unsigned h = (unsigned)i * 2654435761u;
    h ^= h >> 16; h *= 2246822519u; h ^= h >> 13;
    g_v[i] = ((h & 0xFFFFFF) / 16777216.0f) - 0.5f;
}

// out = scale * (in - M@in);  4 warps per row, block = 2 rows
__global__ void matvec_A_kernel(int dst_is_u, float scale) {
    __shared__ float part[8];
    const float* in  = dst_is_u ? g_v : g_u;
    float*       out = dst_is_u ? g_u : g_v;
    int wid = threadIdx.x >> 5, lid = threadIdx.x & 31;
    int row = blockIdx.x * 2 + (wid >> 2);
    int q = wid & 3;
    const __half2* Mrow = (const __half2*)(g_Mhi + (size_t)row * NN);
    float s = 0.f;
    #pragma unroll
    for (int jj = 0; jj < 8; jj++) {
        int j = q * 256 + jj * 32 + lid;
        __half2 m2 = Mrow[j];
        s += __half2float(m2.x) * in[2*j] + __half2float(m2.y) * in[2*j+1];
    }
    #pragma unroll
    for (int o = 16; o > 0; o >>= 1) s += __shfl_xor_sync(0xFFFFFFFFu, s, o);
    if (lid == 0) part[wid] = s;
    __syncthreads();
    if (threadIdx.x < 2) {
        int r = blockIdx.x * 2 + threadIdx.x;
        float t = part[threadIdx.x*4] + part[threadIdx.x*4+1] + part[threadIdx.x*4+2] + part[threadIdx.x*4+3];
        out[r] = scale * (in[r] - t);
    }
}

// sigma^2 -> c + scaled-Newton coefficient schedule
__global__ void dots_and_c_kernel() {
    __shared__ float r0[1024], r1[1024];
    int t = threadIdx.x;
    float a = 0.f, b = 0.f;
    for (int i = t; i < NN; i += 1024) { float vv = g_v[i], uu = g_u[i]; a += vv*vv; b += uu*uu; }
    r0[t] = a; r1[t] = b;
    __syncthreads();
    for (int off = 512; off > 0; off >>= 1) {
        if (t < off) { r0[t] += r0[t+off]; r1[t] += r1[t+off]; }
        __syncthreads();
    }
    if (t == 0) {
        float sigma2 = r1[0] / (r0[0] + 1e-30f);
        float u = 1.6f * sigma2;
        float c = 2.0f / (2.0f + u);
        g_s[2] = c;
        float lo = c, hi = c * (1.0f + u);
        #pragma unroll
        for (int k = 0; k < NSCALED; k++) {
            float s = 2.0f / (lo + hi);
            g_coef[2*k]   = -s * s;
            g_coef[2*k+1] = 2.0f * s;
            float sl = s * lo;
            lo = sl * (2.0f - sl);
            hi = 1.0f;
        }
    }
}

__global__ void init_X0_kernel() {   // X0 = c * M^T  (fp32 + fp16 hi)
    __shared__ float tile[32][33];
    int bx = blockIdx.x * 32, by = blockIdx.y * 32;
    #pragma unroll
    for (int dy = 0; dy < 32; dy += 8)
        tile[threadIdx.y + dy][threadIdx.x] = g_M[(size_t)(by + threadIdx.y + dy) * NN + bx + threadIdx.x];
    __syncthreads();
    float c = g_s[2];
    #pragma unroll
    for (int dy = 0; dy < 32; dy += 8) {
        float v = c * tile[threadIdx.x][threadIdx.y + dy];
        size_t off = (size_t)(bx + threadIdx.y + dy) * NN + by + threadIdx.x;
        g_X[off] = v;
        g_Xh0[off] = __float2half(v);
    }
}

// x fp32 -> xhi (fp16)
__global__ void conv_xhi_kernel(const float* __restrict__ x) {
    size_t i = ((size_t)blockIdx.x * blockDim.x + threadIdx.x) * 4;
    float4 v = *(const float4*)(x + i);
    __half2 h0, h1;
    h0.x = __float2half(v.x); h0.y = __float2half(v.y);
    h1.x = __float2half(v.z); h1.y = __float2half(v.w);
    *(__half2*)(g_xhi + i)     = h0;
    *(__half2*)(g_xhi + i + 2) = h1;
}

// ---------------- mma.sync fp16 GEMM: CTA 128x128, 4 warps (2x2) of 64x64, 5-stage ----------------
// acc[m][n] = sum_k Aseg[m][k] * Bseg'[k][n]
//   BMODE 0: B K-major (row stride NN); BMODE 1: B row-major (row stride Ndim), trans ldmatrix
#define SK 40
#define ASZ (128*SK*2)          // 10240
#define BSZ 10240
#define BT_STRIDE 272
#define NSTAGE 5
#define GSMEM (NSTAGE*(ASZ+BSZ))   // 102400

template<int BMODE>
__global__ void __launch_bounds__(128, 2) mma_gemm_kernel(
    float* outF, __half* outB, __half* outBlo,
    const __half* __restrict__ A0, const __half* __restrict__ A1,
    const __half* __restrict__ A2,
    const __half* __restrict__ B0, const __half* __restrict__ B1,
    const __half* __restrict__ B2,
    const float* __restrict__ Dext, const float* __restrict__ bias,
    const float* __restrict__ coefp,
    int Ndim, int Kdim, float alpha, float beta, int addI)
{
    extern __shared__ __align__(16) char smem[];
    uint32_t sbase = smem_u32(smem);
    int tid = threadIdx.x;
    int wid = tid >> 5, lid = tid & 31;
    int warp_m = wid >> 1, warp_n = wid & 1;      // 2 x 2, warp tile 64x64
    int bm = blockIdx.y * 128, bn = blockIdx.x * 128;

    float acc[4][8][4];
    #pragma unroll
    for (int i = 0; i < 4; i++)
        #pragma unroll
        for (int j = 0; j < 8; j++)
            #pragma unroll
            for (int r = 0; r < 4; r++) acc[i][j][r] = 0.f;

    auto load_stage = [&](int stage, int kt) {
        int seg = kt >> 11;
        int kc0 = kt & (NN - 1);
        const __half* As = (seg == 0) ? A0 : ((seg == 1) ? A1 : A2);
        const __half* Bs = (seg == 0) ? B0 : ((seg == 1) ? B1 : B2);
        uint32_t sA = sbase + stage * (ASZ + BSZ);
        uint32_t sB = sA + ASZ;
        #pragma unroll
        for (int s = 0; s < 4; s++) {               // A: 512 chunks, 128 threads
            int c = tid + s * 128;
            int row = c >> 2, kc = c & 3;
            const char* gA = (const char*)(As + (size_t)(bm + row) * NN + kc0 + kc * 8);
            uint32_t dA = sA + row * (SK*2) + kc * 16;
            asm volatile("cp.async.cg.shared.global [%0], [%1], 16;" :: "r"(dA), "l"(gA));
        }
        #pragma unroll
        for (int s = 0; s < 4; s++) {               // B: 512 chunks
            int c = tid + s * 128;
            if (BMODE == 0) {
                int row = c >> 2, kc = c & 3;
                const char* gB = (const char*)(Bs + (size_t)(bn + row) * NN + kc0 + kc * 8);
                uint32_t dB = sB + row * (SK*2) + kc * 16;
                asm volatile("cp.async.cg.shared.global [%0], [%1], 16;" :: "r"(dB), "l"(gB));
            } else {
                int r = c >> 4, nch = c & 15;
                const char* gB = (const char*)(Bs + (size_t)(kc0 + r) * Ndim + bn + nch * 8);
                uint32_t dB = sB + r * BT_STRIDE + nch * 16;
                asm volatile("cp.async.cg.shared.global [%0], [%1], 16;" :: "r"(dB), "l"(gB));
            }
        }
        asm volatile("cp.async.commit_group;" ::: "memory");
    };

    const int NB = Kdim >> 5;
    #pragma unroll
    for (int s = 0; s < NSTAGE - 1; s++) load_stage(s, s * 32);

    uint32_t a_lane_off = (uint32_t)((lid & 15) * (SK*2) + ((lid >> 4) & 1) * 16);
    uint32_t b_lane_off0 = (uint32_t)((((lid & 7) + ((lid >> 4) & 1) * 8) * (SK*2)) + (((lid >> 3) & 1) * 16));
    int bg = lid >> 3, bw = lid & 7;
    uint32_t bt_krow = (uint32_t)((bg & 1) * 8 + bw);
    uint32_t bt_ncol = (uint32_t)((bg >> 1) * 8);

    for (int kb = 0; kb < NB; kb++) {
        if (kb >= NB - (NSTAGE - 1)) asm volatile("cp.async.wait_group 0;" ::: "memory");
        else                         asm volatile("cp.async.wait_group %0;" :: "n"(NSTAGE - 2) : "memory");
        __syncthreads();

        int nkt = kb + NSTAGE - 1;
        if (nkt < NB) load_stage(nkt % NSTAGE, nkt * 32);

        int stage = kb % NSTAGE;
        uint32_t sA = sbase + stage * (ASZ + BSZ) + warp_m * 64 * (SK*2);
        uint32_t sBb = sbase + stage * (ASZ + BSZ) + ASZ;

        #pragma unroll
        for (int kk = 0; kk < 2; kk++) {
            uint32_t af[4][4], bf[4][4];
            #pragma unroll
            for (int mi = 0; mi < 4; mi++) {
                uint32_t addr = sA + mi * 16 * (SK*2) + kk * 32 + a_lane_off;
                asm volatile("ldmatrix.sync.aligned.m8n8.x4.shared.b16 {%0,%1,%2,%3}, [%4];"
                    : "=r"(af[mi][0]), "=r"(af[mi][1]), "=r"(af[mi][2]), "=r"(af[mi][3]) : "r"(addr));
            }
            #pragma unroll
            for (int nj = 0; nj < 4; nj++) {
                if (BMODE == 0) {
                    uint32_t addr = sBb + (warp_n * 64 + nj * 16) * (SK*2) + kk * 32 + b_lane_off0;
                    asm volatile("ldmatrix.sync.aligned.m8n8.x4.shared.b16 {%0,%1,%2,%3}, [%4];"
                        : "=r"(bf[nj][0]), "=r"(bf[nj][1]), "=r"(bf[nj][2]), "=r"(bf[nj][3]) : "r"(addr));
                } else {
                    uint32_t addr = sBb + (kk * 16 + bt_krow) * BT_STRIDE
                                  + (warp_n * 64 + nj * 16 + bt_ncol) * 2;
                    asm volatile("ldmatrix.sync.aligned.m8n8.x4.trans.shared.b16 {%0,%1,%2,%3}, [%4];"
                        : "=r"(bf[nj][0]), "=r"(bf[nj][1]), "=r"(bf[nj][2]), "=r"(bf[nj][3]) : "r"(addr));
                }
            }
            #pragma unroll
            for (int mi = 0; mi < 4; mi++) {
                #pragma unroll
                for (int nj = 0; nj < 8; nj++) {
                    uint32_t b0 = bf[nj >> 1][(nj & 1) ? 2 : 0];
                    uint32_t b1 = bf[nj >> 1][(nj & 1) ? 3 : 1];
                    asm volatile(
                        "mma.sync.aligned.m16n8k16.row.col.f32.f16.f16.f32 "
                        "{%0,%1,%2,%3}, {%4,%5,%6,%7}, {%8,%9}, {%0,%1,%2,%3};"
                        : "+f"(acc[mi][nj][0]), "+f"(acc[mi][nj][1]),
                          "+f"(acc[mi][nj][2]), "+f"(acc[mi][nj][3])
                        : "r"(af[mi][0]), "r"(af[mi][1]), "r"(af[mi][2]), "r"(af[mi][3]),
                          "r"(b0), "r"(b1));
                }
            }
        }
    }

    if (coefp) { alpha = coefp[0]; beta = coefp[1]; }

    int lrow = lid >> 2, lcol = (lid & 3) * 2;
    #pragma unroll
    for (int mi = 0; mi < 4; mi++) {
        #pragma unroll
        for (int half = 0; half < 2; half++) {
            int row = bm + warp_m * 64 + mi * 16 + lrow + half * 8;
            #pragma unroll
            for (int nj = 0; nj < 8; nj++) {
                int col = bn + warp_n * 64 + nj * 8 + lcol;
                size_t off = (size_t)row * Ndim + col;
                float2 o;
                o.x = alpha * acc[mi][nj][half * 2 + 0];
                o.y = alpha * acc[mi][nj][half * 2 + 1];
                if (Dext) {
                    float2 d2 = *(const float2*)(Dext + off);
                    o.x += beta * d2.x; o.y += beta * d2.y;
                }
                if (bias) {
                    float2 b2 = *(const float2*)(bias + col);
                    o.x += b2.x; o.y += b2.y;
                }
                if (addI) {
                    if (row == col)     o.x += 1.f;
                    if (row == col + 1) o.y += 1.f;
                }
                if (outF) *(float2*)(outF + off) = o;
                if (outB || outBlo) {
                    __half2 h;
                    h.x = __float2half(o.x); h.y = __float2half(o.y);
                    if (outB) *(__half2*)(outB + off) = h;
                    if (outBlo) {
                        __half2 l;
                        l.x = __float2half(o.x - __half2float(h.x));
                        l.y = __float2half(o.y - __half2float(h.y));
                        *(__half2*)(outBlo + off) = l;
                    }
                }
            }
        }
    }
}

// ---------------- launch ----------------
extern "C" void kernel_launch(void* const* d_in, const int* in_sizes, int n_in,
                              void* d_out, int out_size) {
    const float* x      = (const float*)d_in[0];
    const float* weight = (const float*)d_in[1];
    const float* bias   = (const float*)d_in[2];
    float* out = (float*)d_out;

    float *pX, *pY, *pCoef;
    __half *pMhi, *pMlo, *pTbf, *pXh0, *pXh1, *pXl0, *pXl1, *pxhi;
    cudaGetSymbolAddress((void**)&pX, g_X);
    cudaGetSymbolAddress((void**)&pY, g_Y);
    cudaGetSymbolAddress((void**)&pCoef, g_coef);
    cudaGetSymbolAddress((void**)&pMhi, g_Mhi);
    cudaGetSymbolAddress((void**)&pMlo, g_Mlo);
    cudaGetSymbolAddress((void**)&pTbf, g_Tbf);
    cudaGetSymbolAddress((void**)&pXh0, g_Xh0);
    cudaGetSymbolAddress((void**)&pXh1, g_Xh1);
    cudaGetSymbolAddress((void**)&pXl0, g_Xl0);
    cudaGetSymbolAddress((void**)&pXl1, g_Xl1);
    cudaGetSymbolAddress((void**)&pxhi, g_xhi);

    cudaFuncSetAttribute(mma_gemm_kernel<0>, cudaFuncAttributeMaxDynamicSharedMemorySize, GSMEM);
    cudaFuncSetAttribute(mma_gemm_kernel<1>, cudaFuncAttributeMaxDynamicSharedMemorySize, GSMEM);

    // 1. M = I - (w - w^T)
    build_M_kernel<<<dim3(NN/256, NN), 256>>>(weight);

    // 2. power iteration (4 pairs) -> sigma^2, c, schedule
    init_v_kernel<<<NN/256, 256>>>();
    for (int it = 0; it < 4; it++) {
        matvec_A_kernel<<<NN/2, 256>>>(1, 1.0f);
        matvec_A_kernel<<<NN/2, 256>>>(0, 1.0f / 64.0f);
    }
    matvec_A_kernel<<<NN/2, 256>>>(1, 1.0f);
    dots_and_c_kernel<<<1, 1024>>>();

    // 3. X0 = c * M^T
    init_X0_kernel<<<dim3(NN/32, NN/32), dim3(32, 8)>>>();

    dim3 g2k(NN/128, NN/128);          // 256 CTAs
    float *Xf = pX, *Xfn = pY;
    __half *Xb = pXh0, *Xbn = pXh1;
    __half *Xl = pXl0, *Xln = pXl1;

    // 4a. scaled Newton fp16, 5 iters (lo emitted on last)
    for (int it = 0; it < NSCALED; it++) {
        bool last = (it == NSCALED - 1);
        mma_gemm_kernel<1><<<g2k, 128, GSMEM>>>(nullptr, pTbf, nullptr,
                                                pMhi, pMhi, pMhi, Xb, Xb, Xb,
                                                nullptr, nullptr, nullptr,
                                                NN, NN, 1.0f, 0.0f, 0);          // T = M*Xb
        mma_gemm_kernel<1><<<g2k, 128, GSMEM>>>(Xfn, Xbn, last ? Xln : nullptr,
                                                Xb, Xb, Xb, pTbf, pTbf, pTbf,
                                                Xf, nullptr, pCoef + 2*it,
                                                NN, NN, 0.f, 0.f, 0);            // Xn = 2s*X - s^2*Xb*T
        float* tf = Xf; Xf = Xfn; Xfn = tf;
        __half* tb = Xb; Xb = Xbn; Xbn = tb;
        if (last) { __half* tl = Xl; Xl = Xln; Xln = tl; }
    }

    // 4b. polish: R = I - M*(Xhi+Xlo)   (Mhi*Xhi + Mlo*Xhi + Mhi*Xlo, K=6144)
    mma_gemm_kernel<1><<<g2k, 128, GSMEM>>>(nullptr, pTbf, nullptr,
                                            pMhi, pMlo, pMhi, Xb, Xb, Xl,
                                            nullptr, nullptr, nullptr,
                                            NN, 3*NN, -1.0f, 0.0f, 1);
    //   X' = Xf + Xhi*R  (K=2048; Xlo term negligible at O(R)) -> fp16 hi/lo
    mma_gemm_kernel<1><<<g2k, 128, GSMEM>>>(nullptr, Xbn, Xln,
                                            Xb, Xb, Xb, pTbf, pTbf, pTbf,
                                            Xf, nullptr, nullptr,
                                            NN, NN, 1.0f, 1.0f, 0);
    Xb = Xbn; Xl = Xln;

    // 5. out = 2*(x @ X'^T) - x + bias   (xhi*Xhi + xhi*Xlo, K=4096)
    conv_xhi_kernel<<<((size_t)MBIG*NN/4)/256, 256>>>(x);
    mma_gemm_kernel<0><<<dim3(NN/128, MBIG/128), 128, GSMEM>>>(out, nullptr, nullptr,
                                                               pxhi, pxhi, pxhi, Xb, Xl, Xl,
                                                               x, bias, nullptr,
                                                               NN, 2*NN, 2.0f, -1.0f, 0);
}